// round 2
// baseline (speedup 1.0000x reference)
#include <cuda_runtime.h>

// ---------------- problem constants ----------------
#define NEXP   8        // experts
#define DDIM   1024     // model dim
#define HDIM   2048     // hidden dim
#define TMAX   8192     // max tokens (B*S = 4*2048)
#define BM     128
#define BN     128
#define BK     16
#define SLOT_MAX (2*TMAX + NEXP*BM)   // 17408 padded slot rows

// ---------------- device scratch (static, no allocation) ----------------
__device__ int   g_counts[NEXP];
__device__ int   g_fill[NEXP];
__device__ int   g_off[NEXP + 1];          // BM-aligned expert region offsets
__device__ int   g_tok[SLOT_MAX];          // slot -> token index
__device__ int   g_slot[2 * TMAX];         // token,k -> slot
__device__ int   g_e[2 * TMAX];            // token,k -> expert
__device__ float g_wt[2 * TMAX];           // token,k -> gate weight
__device__ float g_h[(size_t)SLOT_MAX * HDIM];   // hidden activations (~142 MB)
__device__ float g_y[(size_t)SLOT_MAX * DDIM];   // expert outputs   (~71 MB)

// ---------------- init ----------------
__global__ void init_kernel() {
    int i = threadIdx.x;
    if (i < NEXP) { g_counts[i] = 0; g_fill[i] = 0; }
}

// ---------------- router: logits -> top2 + normalized weights ----------------
__global__ void router_kernel(const float* __restrict__ x,
                              const float* __restrict__ Wg, int T) {
    int warp = (blockIdx.x * blockDim.x + threadIdx.x) >> 5;
    int lane = threadIdx.x & 31;
    if (warp >= T) return;
    const float* xr = x + (size_t)warp * DDIM;
    float acc[NEXP];
    #pragma unroll
    for (int e = 0; e < NEXP; e++) acc[e] = 0.f;
    for (int d = lane; d < DDIM; d += 32) {
        float xv = xr[d];
        const float* wr = Wg + (size_t)d * NEXP;
        #pragma unroll
        for (int e = 0; e < NEXP; e++) acc[e] += xv * wr[e];
    }
    #pragma unroll
    for (int e = 0; e < NEXP; e++) {
        #pragma unroll
        for (int o = 16; o > 0; o >>= 1)
            acc[e] += __shfl_xor_sync(0xffffffffu, acc[e], o);
    }
    if (lane == 0) {
        int b0 = 0; float l0 = acc[0];
        #pragma unroll
        for (int e = 1; e < NEXP; e++)
            if (acc[e] > l0) { l0 = acc[e]; b0 = e; }
        int b1 = -1; float l1 = -3.0e38f;
        #pragma unroll
        for (int e = 0; e < NEXP; e++)
            if (e != b0 && acc[e] > l1) { l1 = acc[e]; b1 = e; }
        // normalized over top-2: softmax denominator cancels
        float w1 = 1.0f / (1.0f + expf(l0 - l1));
        float w0 = 1.0f - w1;
        g_e[2 * warp]     = b0;  g_e[2 * warp + 1]  = b1;
        g_wt[2 * warp]    = w0;  g_wt[2 * warp + 1] = w1;
        atomicAdd(&g_counts[b0], 1);
        atomicAdd(&g_counts[b1], 1);
    }
}

// ---------------- offsets (tiny, single thread) ----------------
__global__ void offsets_kernel() {
    if (threadIdx.x == 0) {
        g_off[0] = 0;
        #pragma unroll
        for (int e = 0; e < NEXP; e++) {
            int c = g_counts[e];
            g_off[e + 1] = g_off[e] + ((c + BM - 1) / BM) * BM;
            g_fill[e] = 0;
        }
    }
}

// ---------------- scatter tokens into compact per-expert slots ----------------
__global__ void scatter_kernel(int T) {
    int t = blockIdx.x * blockDim.x + threadIdx.x;
    if (t >= T) return;
    #pragma unroll
    for (int k = 0; k < 2; k++) {
        int e   = g_e[2 * t + k];
        int pos = atomicAdd(&g_fill[e], 1);
        int slot = g_off[e] + pos;
        g_tok[slot]       = t;
        g_slot[2 * t + k] = slot;
    }
}

// ---------------- grouped GEMM (SIMT fp32, 128x128x16 tiles, 8x8 micro) ------
// Register-staged prefetch: while FFMAs consume smem tile k0, the next k-tile
// is loaded from global into registers, then committed to smem after a sync.
// GATHER=true : A = x gathered via g_tok, Out = g_h, +b, relu  (K=DDIM,N=HDIM)
// GATHER=false: A = g_h rows,             Out = g_y, +b        (K=HDIM,N=DDIM)
template <int KDIM, int NDIM, bool GATHER, bool RELU>
__global__ void __launch_bounds__(256)
gemm_kernel(const float* __restrict__ Asrc,    // x (GATHER) / unused
            const float* __restrict__ W,       // [E][KDIM][NDIM]
            const float* __restrict__ bias) {  // [E][NDIM]
    __shared__ float As[BK][BM + 4];
    __shared__ float Bs[BK][BN + 4];

    int r0 = blockIdx.y * BM;
    int n0 = blockIdx.x * BN;
    int totalRows = g_off[NEXP];
    if (r0 >= totalRows) return;

    // which expert owns this row block (regions are BM-aligned)
    int e = 0;
    #pragma unroll
    for (int i = 0; i < NEXP; i++)
        if (r0 >= g_off[i + 1]) e = i + 1;
    int cnt  = g_counts[e];
    int base = g_off[e];

    const float* Be = W + (size_t)e * KDIM * NDIM;

    int tid = threadIdx.x;
    int ty = tid >> 4, tx = tid & 15;

    // A-tile loader mapping: 2 passes, thread covers (row, 4 cols)
    int aRow = tid >> 2;          // 0..63
    int aCol = (tid & 3) * 4;     // 0,4,8,12
    const float* aPtr[2];
    #pragma unroll
    for (int p = 0; p < 2; p++) {
        int r = r0 + aRow + p * 64;
        if (GATHER) {
            bool valid = (unsigned)(r - base) < (unsigned)cnt;
            aPtr[p] = valid ? (Asrc + (size_t)g_tok[r] * KDIM) : nullptr;
        } else {
            aPtr[p] = g_h + (size_t)r * KDIM;
        }
    }
    // B-tile loader: 2 passes, thread covers (k row, 4 cols)
    int bRow = tid >> 5;          // 0..7
    int bCol = (tid & 31) * 4;    // 0..124

    float acc[8][8];
    #pragma unroll
    for (int i = 0; i < 8; i++)
        #pragma unroll
        for (int j = 0; j < 8; j++) acc[i][j] = 0.f;

    float4 aNext[2], bNext[2];

    // fetch tile 0 into registers
    #pragma unroll
    for (int p = 0; p < 2; p++) {
        aNext[p] = make_float4(0.f, 0.f, 0.f, 0.f);
        if (aPtr[p]) aNext[p] = *(const float4*)(aPtr[p] + aCol);
        bNext[p] = *(const float4*)(Be + (size_t)(bRow + p * 8) * NDIM + n0 + bCol);
    }

    for (int k0 = 0; k0 < KDIM; k0 += BK) {
        // commit staged registers to smem
        #pragma unroll
        for (int p = 0; p < 2; p++) {
            int m = aRow + p * 64;
            As[aCol + 0][m] = aNext[p].x;
            As[aCol + 1][m] = aNext[p].y;
            As[aCol + 2][m] = aNext[p].z;
            As[aCol + 3][m] = aNext[p].w;
            *(float4*)&Bs[bRow + p * 8][bCol] = bNext[p];
        }
        __syncthreads();

        // prefetch next k-tile into registers (overlaps with FFMA block)
        int kn = k0 + BK;
        if (kn < KDIM) {
            #pragma unroll
            for (int p = 0; p < 2; p++) {
                aNext[p] = make_float4(0.f, 0.f, 0.f, 0.f);
                if (aPtr[p]) aNext[p] = *(const float4*)(aPtr[p] + kn + aCol);
                bNext[p] = *(const float4*)(Be + (size_t)(kn + bRow + p * 8) * NDIM + n0 + bCol);
            }
        }

        // compute on current smem tile
        #pragma unroll
        for (int k = 0; k < BK; k++) {
            float a[8], b[8];
            #pragma unroll
            for (int i = 0; i < 8; i++) {
                a[i] = As[k][ty * 8 + i];
                b[i] = Bs[k][tx * 8 + i];
            }
            #pragma unroll
            for (int i = 0; i < 8; i++)
                #pragma unroll
                for (int j = 0; j < 8; j++)
                    acc[i][j] += a[i] * b[j];
        }
        __syncthreads();
    }

    // epilogue: bias (+relu), write to g_h / g_y
    const float* be = bias + (size_t)e * NDIM;
    float* OutBuf = GATHER ? g_h : g_y;
    #pragma unroll
    for (int i = 0; i < 8; i++) {
        int r = r0 + ty * 8 + i;
        float* orow = OutBuf + (size_t)r * NDIM + n0 + tx * 8;
        #pragma unroll
        for (int j4 = 0; j4 < 2; j4++) {
            float4 v;
            int c = tx * 8 + j4 * 4;
            v.x = acc[i][j4 * 4 + 0] + be[n0 + c + 0];
            v.y = acc[i][j4 * 4 + 1] + be[n0 + c + 1];
            v.z = acc[i][j4 * 4 + 2] + be[n0 + c + 2];
            v.w = acc[i][j4 * 4 + 3] + be[n0 + c + 3];
            if (RELU) {
                v.x = fmaxf(v.x, 0.f); v.y = fmaxf(v.y, 0.f);
                v.z = fmaxf(v.z, 0.f); v.w = fmaxf(v.w, 0.f);
            }
            *(float4*)(orow + j4 * 4) = v;
        }
    }
}

// ---------------- combine: out[t] = w0*y[slot0] + w1*y[slot1] ----------------
__global__ void combine_kernel(float* __restrict__ out, int T) {
    int i = blockIdx.x * blockDim.x + threadIdx.x;
    int nvec = T * (DDIM / 4);
    if (i >= nvec) return;
    int t = i / (DDIM / 4);
    int j = i % (DDIM / 4);
    int s0 = g_slot[2 * t], s1 = g_slot[2 * t + 1];
    float w0 = g_wt[2 * t], w1 = g_wt[2 * t + 1];
    float4 y0 = ((const float4*)(g_y + (size_t)s0 * DDIM))[j];
    float4 y1 = ((const float4*)(g_y + (size_t)s1 * DDIM))[j];
    float4 o;
    o.x = w0 * y0.x + w1 * y1.x;
    o.y = w0 * y0.y + w1 * y1.y;
    o.z = w0 * y0.z + w1 * y1.z;
    o.w = w0 * y0.w + w1 * y1.w;
    ((float4*)out)[i] = o;
}

// ---------------- launch ----------------
extern "C" void kernel_launch(void* const* d_in, const int* in_sizes, int n_in,
                              void* d_out, int out_size) {
    const float* x  = (const float*)d_in[0];
    const float* Wg = (const float*)d_in[1];
    const float* W1 = (const float*)d_in[2];
    const float* b1 = (const float*)d_in[3];
    const float* W2 = (const float*)d_in[4];
    const float* b2 = (const float*)d_in[5];
    float* out = (float*)d_out;
    int T = in_sizes[0] / DDIM;   // 8192

    init_kernel<<<1, 32>>>();
    router_kernel<<<(T + 7) / 8, 256>>>(x, Wg, T);
    offsets_kernel<<<1, 32>>>();
    scatter_kernel<<<(T + 255) / 256, 256>>>(T);

    dim3 grid1(HDIM / BN, SLOT_MAX / BM);   // 16 x 136
    gemm_kernel<DDIM, HDIM, true,  true ><<<grid1, 256>>>(x, W1, b1);

    dim3 grid2(DDIM / BN, SLOT_MAX / BM);   // 8 x 136
    gemm_kernel<HDIM, DDIM, false, false><<<grid2, 256>>>(x, W2, b2);

    int nvec = T * (DDIM / 4);
    combine_kernel<<<(nvec + 255) / 256, 256>>>(out, T);
}

// round 3
// speedup vs baseline: 2.3015x; 2.3015x over previous
#include <cuda_runtime.h>
#include <cstdint>

// ---------------- problem constants ----------------
#define NEXP   8        // experts
#define DDIM   1024     // model dim
#define HDIM   2048     // hidden dim
#define TMAX   8192     // max tokens (B*S = 4*2048)
#define BM     128
#define BN     128
#define BK     32
#define SLOT_MAX (2*TMAX + NEXP*BM)   // 17408 padded slot rows

#define APITCH 36       // As row pitch (u32), 128x36
#define BPITCH 132      // Bs row pitch (u32), 32x132

// ---------------- device scratch (static, no allocation) ----------------
__device__ int   g_counts[NEXP];
__device__ int   g_fill[NEXP];
__device__ int   g_off[NEXP + 1];
__device__ int   g_tok[SLOT_MAX];
__device__ int   g_slot[2 * TMAX];
__device__ int   g_e[2 * TMAX];
__device__ float g_wt[2 * TMAX];
__device__ float g_h[(size_t)SLOT_MAX * HDIM];   // hidden activations
__device__ float g_y[(size_t)SLOT_MAX * DDIM];   // expert outputs

// ---------------- helpers ----------------
__device__ __forceinline__ uint32_t f2tf32(float f) {
    uint32_t r;
    asm("cvt.rna.tf32.f32 %0, %1;" : "=r"(r) : "f"(f));
    return r;
}

__device__ __forceinline__ void mma_tf32(float& c0, float& c1, float& c2, float& c3,
                                         uint32_t a0, uint32_t a1, uint32_t a2, uint32_t a3,
                                         uint32_t b0, uint32_t b1) {
    asm volatile(
        "mma.sync.aligned.m16n8k8.row.col.f32.tf32.tf32.f32 "
        "{%0,%1,%2,%3}, {%4,%5,%6,%7}, {%8,%9}, {%0,%1,%2,%3};"
        : "+f"(c0), "+f"(c1), "+f"(c2), "+f"(c3)
        : "r"(a0), "r"(a1), "r"(a2), "r"(a3), "r"(b0), "r"(b1));
}

// ---------------- init ----------------
__global__ void init_kernel() {
    int i = threadIdx.x;
    if (i < NEXP) { g_counts[i] = 0; g_fill[i] = 0; }
}

// ---------------- router: top-2 + normalized weights ----------------
__global__ void router_kernel(const float* __restrict__ x,
                              const float* __restrict__ Wg, int T) {
    int warp = (blockIdx.x * blockDim.x + threadIdx.x) >> 5;
    int lane = threadIdx.x & 31;
    if (warp >= T) return;
    const float* xr = x + (size_t)warp * DDIM;
    float acc[NEXP];
    #pragma unroll
    for (int e = 0; e < NEXP; e++) acc[e] = 0.f;
    for (int d = lane; d < DDIM; d += 32) {
        float xv = xr[d];
        const float* wr = Wg + (size_t)d * NEXP;
        #pragma unroll
        for (int e = 0; e < NEXP; e++) acc[e] += xv * wr[e];
    }
    #pragma unroll
    for (int e = 0; e < NEXP; e++) {
        #pragma unroll
        for (int o = 16; o > 0; o >>= 1)
            acc[e] += __shfl_xor_sync(0xffffffffu, acc[e], o);
    }
    if (lane == 0) {
        int b0 = 0; float l0 = acc[0];
        #pragma unroll
        for (int e = 1; e < NEXP; e++)
            if (acc[e] > l0) { l0 = acc[e]; b0 = e; }
        int b1 = -1; float l1 = -3.0e38f;
        #pragma unroll
        for (int e = 0; e < NEXP; e++)
            if (e != b0 && acc[e] > l1) { l1 = acc[e]; b1 = e; }
        float w1 = 1.0f / (1.0f + expf(l0 - l1));
        float w0 = 1.0f - w1;
        g_e[2 * warp]     = b0;  g_e[2 * warp + 1]  = b1;
        g_wt[2 * warp]    = w0;  g_wt[2 * warp + 1] = w1;
        atomicAdd(&g_counts[b0], 1);
        atomicAdd(&g_counts[b1], 1);
    }
}

// ---------------- offsets ----------------
__global__ void offsets_kernel() {
    if (threadIdx.x == 0) {
        g_off[0] = 0;
        #pragma unroll
        for (int e = 0; e < NEXP; e++) {
            int c = g_counts[e];
            g_off[e + 1] = g_off[e] + ((c + BM - 1) / BM) * BM;
            g_fill[e] = 0;
        }
    }
}

// ---------------- scatter ----------------
__global__ void scatter_kernel(int T) {
    int t = blockIdx.x * blockDim.x + threadIdx.x;
    if (t >= T) return;
    #pragma unroll
    for (int k = 0; k < 2; k++) {
        int e   = g_e[2 * t + k];
        int pos = atomicAdd(&g_fill[e], 1);
        int slot = g_off[e] + pos;
        g_tok[slot]       = t;
        g_slot[2 * t + k] = slot;
    }
}

// ---------------- grouped GEMM (TF32 tensor cores, 128x128x32) ----------------
// 8 warps, each computes a 64x32 warp tile via m16n8k8 mma.sync.
// fp32 operands are RN-rounded to tf32 (cvt.rna) on the smem-commit path.
// GATHER=true : A = x gathered via g_tok, Out = g_h, +b, relu
// GATHER=false: A = g_h rows,             Out = g_y, +b
template <int KDIM, int NDIM, bool GATHER, bool RELU>
__global__ void __launch_bounds__(256)
gemm_tc_kernel(const float* __restrict__ Asrc,
               const float* __restrict__ W,       // [E][KDIM][NDIM]
               const float* __restrict__ bias) {  // [E][NDIM]
    __shared__ uint32_t As[BM * APITCH];   // [m][k], pitch 36
    __shared__ uint32_t Bs[BK * BPITCH];   // [k][n], pitch 132

    int r0 = blockIdx.y * BM;
    int n0 = blockIdx.x * BN;
    int totalRows = g_off[NEXP];
    if (r0 >= totalRows) return;

    int e = 0;
    #pragma unroll
    for (int i = 0; i < NEXP; i++)
        if (r0 >= g_off[i + 1]) e = i + 1;
    int cnt  = g_counts[e];
    int base = g_off[e];
    const float* Be = W + (size_t)e * KDIM * NDIM;

    int tid  = threadIdx.x;
    int wid  = tid >> 5;
    int lane = tid & 31;
    int g    = lane >> 2;    // 0..7
    int q    = lane & 3;     // 0..3
    int warpM = (wid >> 2) * 64;   // 0 / 64
    int warpN = (wid & 3) * 32;    // 0 / 32 / 64 / 96

    // ---- loaders ----
    // A tile: 128 rows x 32 cols; thread -> row = tid>>1, 16 cols at (tid&1)*16
    int aRow = tid >> 1;
    int aCol = (tid & 1) * 16;
    const float* aP;
    if (GATHER) {
        bool valid = (unsigned)(r0 + aRow - base) < (unsigned)cnt;
        aP = valid ? (Asrc + (size_t)g_tok[r0 + aRow] * KDIM + aCol) : nullptr;
    } else {
        aP = g_h + (size_t)(r0 + aRow) * KDIM + aCol;
    }
    // B tile: 32 rows(k) x 128 cols; thread -> row = tid>>3, 16 cols at (tid&7)*16
    int bRow = tid >> 3;
    int bCol = (tid & 7) * 16;
    const float* bP = Be + (size_t)bRow * NDIM + n0 + bCol;

    float acc[4][4][4];
    #pragma unroll
    for (int mf = 0; mf < 4; mf++)
        #pragma unroll
        for (int nf = 0; nf < 4; nf++)
            #pragma unroll
            for (int c = 0; c < 4; c++) acc[mf][nf][c] = 0.f;

    float4 aN[4], bN[4];
    // prefetch tile 0
    #pragma unroll
    for (int j = 0; j < 4; j++) {
        aN[j] = aP ? *(const float4*)(aP + 4 * j) : make_float4(0.f, 0.f, 0.f, 0.f);
        bN[j] = *(const float4*)(bP + 4 * j);
    }

    for (int k0 = 0; k0 < KDIM; k0 += BK) {
        // commit staged registers to smem (with RN tf32 rounding)
        #pragma unroll
        for (int j = 0; j < 4; j++) {
            uint4 av = make_uint4(f2tf32(aN[j].x), f2tf32(aN[j].y),
                                  f2tf32(aN[j].z), f2tf32(aN[j].w));
            *(uint4*)&As[aRow * APITCH + aCol + 4 * j] = av;
            uint4 bv = make_uint4(f2tf32(bN[j].x), f2tf32(bN[j].y),
                                  f2tf32(bN[j].z), f2tf32(bN[j].w));
            *(uint4*)&Bs[bRow * BPITCH + bCol + 4 * j] = bv;
        }
        __syncthreads();

        // prefetch next k-tile
        int kn = k0 + BK;
        if (kn < KDIM) {
            #pragma unroll
            for (int j = 0; j < 4; j++) {
                aN[j] = aP ? *(const float4*)(aP + kn + 4 * j)
                           : make_float4(0.f, 0.f, 0.f, 0.f);
                bN[j] = *(const float4*)(bP + (size_t)kn * NDIM + 4 * j);
            }
        }

        // compute: 4 k-steps of 8
        #pragma unroll
        for (int ks = 0; ks < 4; ks++) {
            int k8 = ks * 8;
            uint32_t afr[4][4], bfr[4][2];
            #pragma unroll
            for (int mf = 0; mf < 4; mf++) {
                int ab = (warpM + mf * 16 + g) * APITCH + k8 + q;
                afr[mf][0] = As[ab];
                afr[mf][1] = As[ab + 8 * APITCH];
                afr[mf][2] = As[ab + 4];
                afr[mf][3] = As[ab + 8 * APITCH + 4];
            }
            #pragma unroll
            for (int nf = 0; nf < 4; nf++) {
                int bb = (k8 + q) * BPITCH + warpN + nf * 8 + g;
                bfr[nf][0] = Bs[bb];
                bfr[nf][1] = Bs[bb + 4 * BPITCH];
            }
            #pragma unroll
            for (int mf = 0; mf < 4; mf++)
                #pragma unroll
                for (int nf = 0; nf < 4; nf++)
                    mma_tf32(acc[mf][nf][0], acc[mf][nf][1],
                             acc[mf][nf][2], acc[mf][nf][3],
                             afr[mf][0], afr[mf][1], afr[mf][2], afr[mf][3],
                             bfr[nf][0], bfr[nf][1]);
        }
        __syncthreads();
    }

    // ---- epilogue: bias (+relu) ----
    const float* be = bias + (size_t)e * NDIM;
    float* OutBuf = GATHER ? g_h : g_y;
    #pragma unroll
    for (int mf = 0; mf < 4; mf++) {
        int row0 = r0 + warpM + mf * 16 + g;
        int row1 = row0 + 8;
        #pragma unroll
        for (int nf = 0; nf < 4; nf++) {
            int col = n0 + warpN + nf * 8 + q * 2;
            float bv0 = be[col], bv1 = be[col + 1];
            float2 v0, v1;
            v0.x = acc[mf][nf][0] + bv0;  v0.y = acc[mf][nf][1] + bv1;
            v1.x = acc[mf][nf][2] + bv0;  v1.y = acc[mf][nf][3] + bv1;
            if (RELU) {
                v0.x = fmaxf(v0.x, 0.f); v0.y = fmaxf(v0.y, 0.f);
                v1.x = fmaxf(v1.x, 0.f); v1.y = fmaxf(v1.y, 0.f);
            }
            *(float2*)(OutBuf + (size_t)row0 * NDIM + col) = v0;
            *(float2*)(OutBuf + (size_t)row1 * NDIM + col) = v1;
        }
    }
}

// ---------------- combine ----------------
__global__ void combine_kernel(float* __restrict__ out, int T) {
    int i = blockIdx.x * blockDim.x + threadIdx.x;
    int nvec = T * (DDIM / 4);
    if (i >= nvec) return;
    int t = i / (DDIM / 4);
    int j = i % (DDIM / 4);
    int s0 = g_slot[2 * t], s1 = g_slot[2 * t + 1];
    float w0 = g_wt[2 * t], w1 = g_wt[2 * t + 1];
    float4 y0 = ((const float4*)(g_y + (size_t)s0 * DDIM))[j];
    float4 y1 = ((const float4*)(g_y + (size_t)s1 * DDIM))[j];
    float4 o;
    o.x = w0 * y0.x + w1 * y1.x;
    o.y = w0 * y0.y + w1 * y1.y;
    o.z = w0 * y0.z + w1 * y1.z;
    o.w = w0 * y0.w + w1 * y1.w;
    ((float4*)out)[i] = o;
}

// ---------------- launch ----------------
extern "C" void kernel_launch(void* const* d_in, const int* in_sizes, int n_in,
                              void* d_out, int out_size) {
    const float* x  = (const float*)d_in[0];
    const float* Wg = (const float*)d_in[1];
    const float* W1 = (const float*)d_in[2];
    const float* b1 = (const float*)d_in[3];
    const float* W2 = (const float*)d_in[4];
    const float* b2 = (const float*)d_in[5];
    float* out = (float*)d_out;
    int T = in_sizes[0] / DDIM;   // 8192

    init_kernel<<<1, 32>>>();
    router_kernel<<<(T + 7) / 8, 256>>>(x, Wg, T);
    offsets_kernel<<<1, 32>>>();
    scatter_kernel<<<(T + 255) / 256, 256>>>(T);

    dim3 grid1(HDIM / BN, SLOT_MAX / BM);   // 16 x 136
    gemm_tc_kernel<DDIM, HDIM, true,  true ><<<grid1, 256>>>(x, W1, b1);

    dim3 grid2(DDIM / BN, SLOT_MAX / BM);   // 8 x 136
    gemm_tc_kernel<HDIM, DDIM, false, false><<<grid2, 256>>>(x, W2, b2);

    int nvec = T * (DDIM / 4);
    combine_kernel<<<(nvec + 255) / 256, 256>>>(out, T);
}